// round 13
// baseline (speedup 1.0000x reference)
#include <cuda_runtime.h>
#include <cuda_bf16.h>
#include <math.h>
#include <stdint.h>

// ---------------------------------------------------------------------------
// GemmaMoELayer: two Gemma decoder layers (a/b) + mix attention over
// concatenated pre-RoPE q/k/v, outputs stacked [2, S, HID] fp32.
// All GEMMs on tensor cores via mma.sync tf32 (fp32 accumulate).
// B=1, S=2048, HID=1024, NH=8, HD=128, INTER=4096
// ---------------------------------------------------------------------------

#define S_LEN 2048
#define HID 1024
#define NH 8
#define HD 128
#define INTER 4096
#define S2 (2 * S_LEN)   // 4096

// ------------------------- scratch (device globals) ------------------------
__device__ float g_h[S_LEN * HID];                 // rmsnorm output
__device__ float g_q[S2 * HID];                    // pre-RoPE q, both experts
__device__ float g_k[S2 * HID];
__device__ float g_v[S2 * HID];
__device__ float g_qr[S_LEN * HID];                // post-RoPE (per expert)
__device__ float g_kr[S_LEN * HID];
__device__ float g_scores[(long long)NH * S2 * S2];  // 536 MB, reused
__device__ float g_attn[S2 * HID];
__device__ float g_h1[2 * S_LEN * HID];
__device__ float g_m[S_LEN * HID];
__device__ float g_gate[S_LEN * INTER];
__device__ float g_up[S_LEN * INTER];

// ----------------------------- tf32 helpers --------------------------------
__device__ __forceinline__ uint32_t f2tf(float f) {
    uint32_t u;
    asm("cvt.rna.tf32.f32 %0, %1;" : "=r"(u) : "f"(f));
    return u;
}

__device__ __forceinline__ void mma_tf32(float* c, const uint32_t* a,
                                         const uint32_t* b) {
    asm volatile(
        "mma.sync.aligned.m16n8k8.row.col.f32.tf32.tf32.f32 "
        "{%0,%1,%2,%3}, {%4,%5,%6,%7}, {%8,%9}, {%0,%1,%2,%3};\n"
        : "+f"(c[0]), "+f"(c[1]), "+f"(c[2]), "+f"(c[3])
        : "r"(a[0]), "r"(a[1]), "r"(a[2]), "r"(a[3]),
          "r"(b[0]), "r"(b[1]));
}

// --------------------------- TF32 GEMM kernel ------------------------------
// C[m,n] = alpha * sum_k A[m,k] * (TB ? B[n,k] : B[k,n]) (+Msk) (+D)
// Block tile 128x128, K-tile 16, 256 threads (8 warps: 2 m-rows x 4 n-cols,
// warp tile 64x32). M,N % 128 == 0, K % 16 == 0. Batched via blockIdx.z.
template <bool TB>
__global__ __launch_bounds__(256, 1)
void tf32_gemm(const float* __restrict__ A, int lda, long long sA,
               const float* __restrict__ B, int ldb, long long sB,
               float* __restrict__ C, int ldc, long long sC,
               const float* __restrict__ D, int ldd, long long sD,
               const float* __restrict__ Msk, int ldm,
               float alpha, int M, int N, int K)
{
    __shared__ uint32_t As[2][16][136];   // [k][m], pad 8 -> conflict-free frags
    __shared__ uint32_t Bs[2][16][136];   // [k][n]

    const int bz = blockIdx.z;
    A += bz * sA;
    B += bz * sB;
    C += bz * sC;
    if (D) D += bz * sD;

    const int tid  = threadIdx.x;
    const int warp = tid >> 5, lane = tid & 31;
    const int gid  = lane >> 2, tig = lane & 3;
    const int wm   = (warp >> 2) * 64;    // 0 / 64
    const int wn   = (warp & 3) * 32;     // 0 / 32 / 64 / 96
    const int m0   = blockIdx.y * 128;
    const int n0   = blockIdx.x * 128;

    // staging thread mapping
    const int ar = tid >> 2;             // 0..63 (A rows; + second pass +64)
    const int ac = (tid & 3) * 4;        // k offset within tile
    int br, bc;
    if (TB) { br = tid >> 2;  bc = (tid & 3) * 4;  }  // br = n idx, bc = k
    else    { br = tid >> 4;  bc = (tid & 15) * 4; }  // br = k idx, bc = n

    float acc[4][4][4] = {};

    float4 ga[2], gb[2];

    // ---- prologue: load k-tile 0 ----
    ga[0] = *reinterpret_cast<const float4*>(&A[(long long)(m0 + ar) * lda + ac]);
    ga[1] = *reinterpret_cast<const float4*>(&A[(long long)(m0 + ar + 64) * lda + ac]);
    if (TB) {
        gb[0] = *reinterpret_cast<const float4*>(&B[(long long)(n0 + br) * ldb + bc]);
        gb[1] = *reinterpret_cast<const float4*>(&B[(long long)(n0 + br + 64) * ldb + bc]);
    } else {
        gb[0] = *reinterpret_cast<const float4*>(&B[(long long)br * ldb + n0 + bc]);
        gb[1] = *reinterpret_cast<const float4*>(&B[(long long)br * ldb + n0 + bc + 64]);
    }

    {
        float a0[4] = {ga[0].x, ga[0].y, ga[0].z, ga[0].w};
        float a1[4] = {ga[1].x, ga[1].y, ga[1].z, ga[1].w};
        float b0[4] = {gb[0].x, gb[0].y, gb[0].z, gb[0].w};
        float b1[4] = {gb[1].x, gb[1].y, gb[1].z, gb[1].w};
#pragma unroll
        for (int u = 0; u < 4; u++) {
            As[0][ac + u][ar]      = f2tf(a0[u]);
            As[0][ac + u][ar + 64] = f2tf(a1[u]);
            if (TB) {
                Bs[0][bc + u][br]      = f2tf(b0[u]);
                Bs[0][bc + u][br + 64] = f2tf(b1[u]);
            } else {
                Bs[0][br][bc + u]      = f2tf(b0[u]);
                Bs[0][br][bc + 64 + u] = f2tf(b1[u]);
            }
        }
    }
    __syncthreads();

    const int nk = K >> 4;
    for (int kt = 0; kt < nk; kt++) {
        const int buf = kt & 1;
        const bool more = (kt + 1 < nk);

        // issue next tile's global loads (latency hidden by compute below)
        if (more) {
            const int kn = (kt + 1) << 4;
            ga[0] = *reinterpret_cast<const float4*>(&A[(long long)(m0 + ar) * lda + kn + ac]);
            ga[1] = *reinterpret_cast<const float4*>(&A[(long long)(m0 + ar + 64) * lda + kn + ac]);
            if (TB) {
                gb[0] = *reinterpret_cast<const float4*>(&B[(long long)(n0 + br) * ldb + kn + bc]);
                gb[1] = *reinterpret_cast<const float4*>(&B[(long long)(n0 + br + 64) * ldb + kn + bc]);
            } else {
                gb[0] = *reinterpret_cast<const float4*>(&B[(long long)(kn + br) * ldb + n0 + bc]);
                gb[1] = *reinterpret_cast<const float4*>(&B[(long long)(kn + br) * ldb + n0 + bc + 64]);
            }
        }

        // ---- compute on current buffer: 2 k-steps of 8 ----
#pragma unroll
        for (int ks = 0; ks < 2; ks++) {
            const int kk = ks * 8;
            uint32_t af[4][4], bf[4][2];
#pragma unroll
            for (int i = 0; i < 4; i++) {
                const int m = wm + i * 16 + gid;
                af[i][0] = As[buf][kk + tig][m];
                af[i][1] = As[buf][kk + tig][m + 8];
                af[i][2] = As[buf][kk + tig + 4][m];
                af[i][3] = As[buf][kk + tig + 4][m + 8];
            }
#pragma unroll
            for (int j = 0; j < 4; j++) {
                const int n = wn + j * 8 + gid;
                bf[j][0] = Bs[buf][kk + tig][n];
                bf[j][1] = Bs[buf][kk + tig + 4][n];
            }
#pragma unroll
            for (int i = 0; i < 4; i++)
#pragma unroll
                for (int j = 0; j < 4; j++)
                    mma_tf32(acc[i][j], af[i], bf[j]);
        }

        // ---- stage next tile ----
        if (more) {
            const int nb = buf ^ 1;
            float a0[4] = {ga[0].x, ga[0].y, ga[0].z, ga[0].w};
            float a1[4] = {ga[1].x, ga[1].y, ga[1].z, ga[1].w};
            float b0[4] = {gb[0].x, gb[0].y, gb[0].z, gb[0].w};
            float b1[4] = {gb[1].x, gb[1].y, gb[1].z, gb[1].w};
#pragma unroll
            for (int u = 0; u < 4; u++) {
                As[nb][ac + u][ar]      = f2tf(a0[u]);
                As[nb][ac + u][ar + 64] = f2tf(a1[u]);
                if (TB) {
                    Bs[nb][bc + u][br]      = f2tf(b0[u]);
                    Bs[nb][bc + u][br + 64] = f2tf(b1[u]);
                } else {
                    Bs[nb][br][bc + u]      = f2tf(b0[u]);
                    Bs[nb][br][bc + 64 + u] = f2tf(b1[u]);
                }
            }
        }
        __syncthreads();
    }

    // -------- epilogue --------
#pragma unroll
    for (int i = 0; i < 4; i++) {
#pragma unroll
        for (int j = 0; j < 4; j++) {
            const int m = m0 + wm + i * 16 + gid;
            const int n = n0 + wn + j * 8 + tig * 2;
            float2 r0 = make_float2(acc[i][j][0] * alpha, acc[i][j][1] * alpha);
            float2 r1 = make_float2(acc[i][j][2] * alpha, acc[i][j][3] * alpha);
            if (Msk) {
                r0.x += Msk[(long long)m * ldm + n];
                r0.y += Msk[(long long)m * ldm + n + 1];
                r1.x += Msk[(long long)(m + 8) * ldm + n];
                r1.y += Msk[(long long)(m + 8) * ldm + n + 1];
            }
            if (D) {
                r0.x += D[(long long)m * ldd + n];
                r0.y += D[(long long)m * ldd + n + 1];
                r1.x += D[(long long)(m + 8) * ldd + n];
                r1.y += D[(long long)(m + 8) * ldd + n + 1];
            }
            *reinterpret_cast<float2*>(&C[(long long)m * ldc + n]) = r0;
            *reinterpret_cast<float2*>(&C[(long long)(m + 8) * ldc + n]) = r1;
        }
    }
}

// --------------------------- elementwise kernels ---------------------------
__global__ void rmsnorm_kernel(const float* __restrict__ x,
                               const float* __restrict__ w,
                               float* __restrict__ out, int ncols)
{
    int row = blockIdx.x;
    const float* xr = x + (long long)row * ncols;
    float* orow = out + (long long)row * ncols;
    __shared__ float red[256];
    int tid = threadIdx.x;
    float s = 0.f;
    for (int i = tid; i < ncols; i += 256) { float v = xr[i]; s += v * v; }
    red[tid] = s; __syncthreads();
    for (int k = 128; k > 0; k >>= 1) {
        if (tid < k) red[tid] += red[tid + k];
        __syncthreads();
    }
    float scale = rsqrtf(red[0] / (float)ncols + 1e-6f);
    for (int i = tid; i < ncols; i += 256)
        orow[i] = xr[i] * scale * (1.0f + w[i]);
}

__global__ void rope_kernel(const float* __restrict__ q, const float* __restrict__ k,
                            float* __restrict__ qr, float* __restrict__ kr)
{
    int s = blockIdx.x;                              // 0..S-1
    int idx = blockIdx.y * 256 + threadIdx.x;        // 0..1023 (NH*HD)
    int d = idx & (HD - 1);
    long long base = (long long)s * HID + idx;
    int i = d & 63;
    float freq = powf(10000.0f, -(float)i / 64.0f);
    float ang = (float)s * freq;
    float c = cosf(ang), sn = sinf(ang);
    float qv = q[base], kv = k[base];
    float qo, ko;
    if (d < 64) {
        qo = qv * c - q[base + 64] * sn;
        ko = kv * c - k[base + 64] * sn;
    } else {
        qo = qv * c + q[base - 64] * sn;
        ko = kv * c + k[base - 64] * sn;
    }
    qr[base] = qo;
    kr[base] = ko;
}

__global__ void softmax_rows(float* __restrict__ S, int len)
{
    long long row = blockIdx.x;
    float4* p = reinterpret_cast<float4*>(S + row * (long long)len);
    int n4 = len >> 2;
    __shared__ float red[256];
    int tid = threadIdx.x;

    float mx = -1e30f;
    for (int i = tid; i < n4; i += 256) {
        float4 v = p[i];
        mx = fmaxf(mx, fmaxf(fmaxf(v.x, v.y), fmaxf(v.z, v.w)));
    }
    red[tid] = mx; __syncthreads();
    for (int k = 128; k > 0; k >>= 1) {
        if (tid < k) red[tid] = fmaxf(red[tid], red[tid + k]);
        __syncthreads();
    }
    mx = red[0];
    __syncthreads();

    float sum = 0.f;
    for (int i = tid; i < n4; i += 256) {
        float4 v = p[i];
        v.x = __expf(v.x - mx); v.y = __expf(v.y - mx);
        v.z = __expf(v.z - mx); v.w = __expf(v.w - mx);
        p[i] = v;
        sum += v.x + v.y + v.z + v.w;
    }
    red[tid] = sum; __syncthreads();
    for (int k = 128; k > 0; k >>= 1) {
        if (tid < k) red[tid] += red[tid + k];
        __syncthreads();
    }
    float inv = 1.0f / red[0];
    for (int i = tid; i < n4; i += 256) {
        float4 v = p[i];
        v.x *= inv; v.y *= inv; v.z *= inv; v.w *= inv;
        p[i] = v;
    }
}

__global__ void gelumul_kernel(float* __restrict__ g, const float* __restrict__ u,
                               long long n)
{
    long long i = (long long)blockIdx.x * 256 + threadIdx.x;
    if (i < n) {
        float x = g[i];
        float t = tanhf(0.7978845608028654f * (x + 0.044715f * x * x * x));
        g[i] = 0.5f * x * (1.0f + t) * u[i];
    }
}

// ------------------------------- host side ---------------------------------
static inline void gemm_nn(const float* A, int lda, long long sA,
                           const float* B, int ldb, long long sB,
                           float* C, int ldc, long long sC,
                           const float* D, int ldd, long long sD,
                           const float* Msk, int ldm,
                           float alpha, int M, int N, int K, int batch)
{
    dim3 grid(N / 128, M / 128, batch);
    tf32_gemm<false><<<grid, 256>>>(A, lda, sA, B, ldb, sB, C, ldc, sC,
                                    D, ldd, sD, Msk, ldm, alpha, M, N, K);
}

static inline void gemm_nt(const float* A, int lda, long long sA,
                           const float* B, int ldb, long long sB,
                           float* C, int ldc, long long sC,
                           const float* Msk, int ldm,
                           float alpha, int M, int N, int K, int batch)
{
    dim3 grid(N / 128, M / 128, batch);
    tf32_gemm<true><<<grid, 256>>>(A, lda, sA, B, ldb, sB, C, ldc, sC,
                                   (const float*)nullptr, 0, 0, Msk, ldm,
                                   alpha, M, N, K);
}

extern "C" void kernel_launch(void* const* d_in, const int* in_sizes, int n_in,
                              void* d_out, int out_size)
{
    (void)in_sizes; (void)n_in; (void)out_size;

    const float* x[2]    = { (const float*)d_in[0], (const float*)d_in[1] };
    const float* mask[2] = { (const float*)d_in[2], (const float*)d_in[3] };
    const float* mixmask = (const float*)d_in[4];
    float* out = (float*)d_out;

    float *p_h, *p_q, *p_k, *p_v, *p_qr, *p_kr, *p_sc, *p_at, *p_h1, *p_m, *p_g, *p_u;
    cudaGetSymbolAddress((void**)&p_h,  g_h);
    cudaGetSymbolAddress((void**)&p_q,  g_q);
    cudaGetSymbolAddress((void**)&p_k,  g_k);
    cudaGetSymbolAddress((void**)&p_v,  g_v);
    cudaGetSymbolAddress((void**)&p_qr, g_qr);
    cudaGetSymbolAddress((void**)&p_kr, g_kr);
    cudaGetSymbolAddress((void**)&p_sc, g_scores);
    cudaGetSymbolAddress((void**)&p_at, g_attn);
    cudaGetSymbolAddress((void**)&p_h1, g_h1);
    cudaGetSymbolAddress((void**)&p_m,  g_m);
    cudaGetSymbolAddress((void**)&p_g,  g_gate);
    cudaGetSymbolAddress((void**)&p_u,  g_up);

    const float att_scale = 0.08838834764831845f;   // 1/sqrt(128)
    const long long EOFF = (long long)S_LEN * HID;

    for (int e = 0; e < 2; e++) {
        const float* w_ln  = (const float*)d_in[5 + 9 * e + 0];
        const float* w_q   = (const float*)d_in[5 + 9 * e + 1];
        const float* w_k   = (const float*)d_in[5 + 9 * e + 2];
        const float* w_v   = (const float*)d_in[5 + 9 * e + 3];
        const float* w_o   = (const float*)d_in[5 + 9 * e + 4];
        const float* w_pln = (const float*)d_in[5 + 9 * e + 5];
        const float* w_g   = (const float*)d_in[5 + 9 * e + 6];
        const float* w_u   = (const float*)d_in[5 + 9 * e + 7];
        const float* w_d   = (const float*)d_in[5 + 9 * e + 8];

        float* q_e = p_q + e * EOFF;
        float* k_e = p_k + e * EOFF;
        float* v_e = p_v + e * EOFF;
        float* h1_e = p_h1 + e * EOFF;
        float* out_e = out + e * EOFF;

        // 1. pre-attention RMSNorm
        rmsnorm_kernel<<<S_LEN, 256>>>(x[e], w_ln, p_h, HID);

        // 2. q/k/v projections (pre-RoPE, kept for mix attention)
        gemm_nn(p_h, HID, 0, w_q, HID, 0, q_e, HID, 0,
                nullptr, 0, 0, nullptr, 0, 1.0f, S_LEN, HID, HID, 1);
        gemm_nn(p_h, HID, 0, w_k, HID, 0, k_e, HID, 0,
                nullptr, 0, 0, nullptr, 0, 1.0f, S_LEN, HID, HID, 1);
        gemm_nn(p_h, HID, 0, w_v, HID, 0, v_e, HID, 0,
                nullptr, 0, 0, nullptr, 0, 1.0f, S_LEN, HID, HID, 1);

        // 3. RoPE
        rope_kernel<<<dim3(S_LEN, 4), 256>>>(q_e, k_e, p_qr, p_kr);

        // 4. scores = qr @ kr^T * scale + mask   (batched over heads)
        gemm_nt(p_qr, HID, HD, p_kr, HID, HD,
                p_sc, S_LEN, (long long)S_LEN * S_LEN,
                mask[e], S_LEN, att_scale, S_LEN, S_LEN, HD, NH);

        // 5. softmax
        softmax_rows<<<NH * S_LEN, 256>>>(p_sc, S_LEN);

        // 6. attn = probs @ v    (batched over heads)
        gemm_nn(p_sc, S_LEN, (long long)S_LEN * S_LEN,
                v_e, HID, HD,
                p_at, HID, HD,
                nullptr, 0, 0, nullptr, 0, 1.0f, S_LEN, HD, S_LEN, NH);

        // 7. h1 = attn @ w_o + x
        gemm_nn(p_at, HID, 0, w_o, HID, 0, h1_e, HID, 0,
                x[e], HID, 0, nullptr, 0, 1.0f, S_LEN, HID, HID, 1);

        // 8. post-attention RMSNorm
        rmsnorm_kernel<<<S_LEN, 256>>>(h1_e, w_pln, p_m, HID);

        // 9. MLP
        gemm_nn(p_m, HID, 0, w_g, INTER, 0, p_g, INTER, 0,
                nullptr, 0, 0, nullptr, 0, 1.0f, S_LEN, INTER, HID, 1);
        gemm_nn(p_m, HID, 0, w_u, INTER, 0, p_u, INTER, 0,
                nullptr, 0, 0, nullptr, 0, 1.0f, S_LEN, INTER, HID, 1);
        gelumul_kernel<<<(S_LEN * INTER) / 256, 256>>>(p_g, p_u,
                                                       (long long)S_LEN * INTER);
        gemm_nn(p_g, INTER, 0, w_d, HID, 0, out_e, HID, 0,
                h1_e, HID, 0, nullptr, 0, 1.0f, S_LEN, HID, INTER, 1);
    }

    // ----- mix attention over concatenated PRE-RoPE q/k/v -----
    gemm_nt(p_q, HID, HD, p_k, HID, HD,
            p_sc, S2, (long long)S2 * S2,
            mixmask, S2, att_scale, S2, S2, HD, NH);
    softmax_rows<<<NH * S2, 256>>>(p_sc, S2);
    gemm_nn(p_sc, S2, (long long)S2 * S2,
            p_v, HID, HD,
            p_at, HID, HD,
            nullptr, 0, 0, nullptr, 0, 1.0f, S2, HD, S2, NH);

    // final: out_e += mixed_e @ w_o_e
    for (int e = 0; e < 2; e++) {
        const float* w_o = (const float*)d_in[5 + 9 * e + 4];
        float* out_e = out + e * EOFF;
        gemm_nn(p_at + e * EOFF, HID, 0, w_o, HID, 0, out_e, HID, 0,
                out_e, HID, 0, nullptr, 0, 1.0f, S_LEN, HID, HID, 1);
    }
}

// round 14
// speedup vs baseline: 1.0001x; 1.0001x over previous
#include <cuda_runtime.h>
#include <cuda_bf16.h>
#include <math.h>
#include <stdint.h>

// ---------------------------------------------------------------------------
// GemmaMoELayer: two Gemma decoder layers (a/b) + mix attention over
// concatenated pre-RoPE q/k/v, outputs stacked [2, S, HID] fp32.
// All GEMMs on tensor cores via mma.sync tf32 (fp32 accumulate).
// B=1, S=2048, HID=1024, NH=8, HD=128, INTER=4096
// ---------------------------------------------------------------------------

#define S_LEN 2048
#define HID 1024
#define NH 8
#define HD 128
#define INTER 4096
#define S2 (2 * S_LEN)   // 4096

// ------------------------- scratch (device globals) ------------------------
__device__ float g_h[S_LEN * HID];                 // rmsnorm output
__device__ float g_q[S2 * HID];                    // pre-RoPE q, both experts
__device__ float g_k[S2 * HID];
__device__ float g_v[S2 * HID];
__device__ float g_qr[S_LEN * HID];                // post-RoPE (per expert)
__device__ float g_kr[S_LEN * HID];
__device__ float g_scores[(long long)NH * S2 * S2];  // 536 MB, reused
__device__ float g_attn[S2 * HID];
__device__ float g_h1[2 * S_LEN * HID];
__device__ float g_m[S_LEN * HID];
__device__ float g_gate[S_LEN * INTER];
__device__ float g_up[S_LEN * INTER];

// ----------------------------- tf32 helpers --------------------------------
__device__ __forceinline__ uint32_t f2tf(float f) {
    uint32_t u;
    asm("cvt.rna.tf32.f32 %0, %1;" : "=r"(u) : "f"(f));
    return u;
}

__device__ __forceinline__ void mma_tf32(float* c, const uint32_t* a,
                                         const uint32_t* b) {
    asm volatile(
        "mma.sync.aligned.m16n8k8.row.col.f32.tf32.tf32.f32 "
        "{%0,%1,%2,%3}, {%4,%5,%6,%7}, {%8,%9}, {%0,%1,%2,%3};\n"
        : "+f"(c[0]), "+f"(c[1]), "+f"(c[2]), "+f"(c[3])
        : "r"(a[0]), "r"(a[1]), "r"(a[2]), "r"(a[3]),
          "r"(b[0]), "r"(b[1]));
}

// --------------------------- TF32 GEMM kernel ------------------------------
// C[m,n] = alpha * sum_k A[m,k] * (TB ? B[n,k] : B[k,n]) (+Msk) (+D)
// Block tile 128x128, K-tile 16, 256 threads (8 warps: 2 m-rows x 4 n-cols,
// warp tile 64x32). M,N % 128 == 0, K % 16 == 0. Batched via blockIdx.z.
template <bool TB>
__global__ __launch_bounds__(256, 1)
void tf32_gemm(const float* __restrict__ A, int lda, long long sA,
               const float* __restrict__ B, int ldb, long long sB,
               float* __restrict__ C, int ldc, long long sC,
               const float* __restrict__ D, int ldd, long long sD,
               const float* __restrict__ Msk, int ldm,
               float alpha, int M, int N, int K)
{
    __shared__ uint32_t As[2][16][136];   // [k][m], pad 8 -> conflict-free frags
    __shared__ uint32_t Bs[2][16][136];   // [k][n]

    const int bz = blockIdx.z;
    A += bz * sA;
    B += bz * sB;
    C += bz * sC;
    if (D) D += bz * sD;

    const int tid  = threadIdx.x;
    const int warp = tid >> 5, lane = tid & 31;
    const int gid  = lane >> 2, tig = lane & 3;
    const int wm   = (warp >> 2) * 64;    // 0 / 64
    const int wn   = (warp & 3) * 32;     // 0 / 32 / 64 / 96
    const int m0   = blockIdx.y * 128;
    const int n0   = blockIdx.x * 128;

    // staging thread mapping
    const int ar = tid >> 2;             // 0..63 (A rows; + second pass +64)
    const int ac = (tid & 3) * 4;        // k offset within tile
    int br, bc;
    if (TB) { br = tid >> 2;  bc = (tid & 3) * 4;  }  // br = n idx, bc = k
    else    { br = tid >> 4;  bc = (tid & 15) * 4; }  // br = k idx, bc = n

    float acc[4][4][4] = {};

    float4 ga[2], gb[2];

    // ---- prologue: load k-tile 0 ----
    ga[0] = *reinterpret_cast<const float4*>(&A[(long long)(m0 + ar) * lda + ac]);
    ga[1] = *reinterpret_cast<const float4*>(&A[(long long)(m0 + ar + 64) * lda + ac]);
    if (TB) {
        gb[0] = *reinterpret_cast<const float4*>(&B[(long long)(n0 + br) * ldb + bc]);
        gb[1] = *reinterpret_cast<const float4*>(&B[(long long)(n0 + br + 64) * ldb + bc]);
    } else {
        gb[0] = *reinterpret_cast<const float4*>(&B[(long long)br * ldb + n0 + bc]);
        gb[1] = *reinterpret_cast<const float4*>(&B[(long long)br * ldb + n0 + bc + 64]);
    }

    {
        float a0[4] = {ga[0].x, ga[0].y, ga[0].z, ga[0].w};
        float a1[4] = {ga[1].x, ga[1].y, ga[1].z, ga[1].w};
        float b0[4] = {gb[0].x, gb[0].y, gb[0].z, gb[0].w};
        float b1[4] = {gb[1].x, gb[1].y, gb[1].z, gb[1].w};
#pragma unroll
        for (int u = 0; u < 4; u++) {
            As[0][ac + u][ar]      = f2tf(a0[u]);
            As[0][ac + u][ar + 64] = f2tf(a1[u]);
            if (TB) {
                Bs[0][bc + u][br]      = f2tf(b0[u]);
                Bs[0][bc + u][br + 64] = f2tf(b1[u]);
            } else {
                Bs[0][br][bc + u]      = f2tf(b0[u]);
                Bs[0][br][bc + 64 + u] = f2tf(b1[u]);
            }
        }
    }
    __syncthreads();

    const int nk = K >> 4;
    for (int kt = 0; kt < nk; kt++) {
        const int buf = kt & 1;
        const bool more = (kt + 1 < nk);

        // issue next tile's global loads (latency hidden by compute below)
        if (more) {
            const int kn = (kt + 1) << 4;
            ga[0] = *reinterpret_cast<const float4*>(&A[(long long)(m0 + ar) * lda + kn + ac]);
            ga[1] = *reinterpret_cast<const float4*>(&A[(long long)(m0 + ar + 64) * lda + kn + ac]);
            if (TB) {
                gb[0] = *reinterpret_cast<const float4*>(&B[(long long)(n0 + br) * ldb + kn + bc]);
                gb[1] = *reinterpret_cast<const float4*>(&B[(long long)(n0 + br + 64) * ldb + kn + bc]);
            } else {
                gb[0] = *reinterpret_cast<const float4*>(&B[(long long)(kn + br) * ldb + n0 + bc]);
                gb[1] = *reinterpret_cast<const float4*>(&B[(long long)(kn + br) * ldb + n0 + bc + 64]);
            }
        }

        // ---- compute on current buffer: 2 k-steps of 8 ----
#pragma unroll
        for (int ks = 0; ks < 2; ks++) {
            const int kk = ks * 8;
            uint32_t af[4][4], bf[4][2];
#pragma unroll
            for (int i = 0; i < 4; i++) {
                const int m = wm + i * 16 + gid;
                af[i][0] = As[buf][kk + tig][m];
                af[i][1] = As[buf][kk + tig][m + 8];
                af[i][2] = As[buf][kk + tig + 4][m];
                af[i][3] = As[buf][kk + tig + 4][m + 8];
            }
#pragma unroll
            for (int j = 0; j < 4; j++) {
                const int n = wn + j * 8 + gid;
                bf[j][0] = Bs[buf][kk + tig][n];
                bf[j][1] = Bs[buf][kk + tig + 4][n];
            }
#pragma unroll
            for (int i = 0; i < 4; i++)
#pragma unroll
                for (int j = 0; j < 4; j++)
                    mma_tf32(acc[i][j], af[i], bf[j]);
        }

        // ---- stage next tile ----
        if (more) {
            const int nb = buf ^ 1;
            float a0[4] = {ga[0].x, ga[0].y, ga[0].z, ga[0].w};
            float a1[4] = {ga[1].x, ga[1].y, ga[1].z, ga[1].w};
            float b0[4] = {gb[0].x, gb[0].y, gb[0].z, gb[0].w};
            float b1[4] = {gb[1].x, gb[1].y, gb[1].z, gb[1].w};
#pragma unroll
            for (int u = 0; u < 4; u++) {
                As[nb][ac + u][ar]      = f2tf(a0[u]);
                As[nb][ac + u][ar + 64] = f2tf(a1[u]);
                if (TB) {
                    Bs[nb][bc + u][br]      = f2tf(b0[u]);
                    Bs[nb][bc + u][br + 64] = f2tf(b1[u]);
                } else {
                    Bs[nb][br][bc + u]      = f2tf(b0[u]);
                    Bs[nb][br][bc + 64 + u] = f2tf(b1[u]);
                }
            }
        }
        __syncthreads();
    }

    // -------- epilogue --------
#pragma unroll
    for (int i = 0; i < 4; i++) {
#pragma unroll
        for (int j = 0; j < 4; j++) {
            const int m = m0 + wm + i * 16 + gid;
            const int n = n0 + wn + j * 8 + tig * 2;
            float2 r0 = make_float2(acc[i][j][0] * alpha, acc[i][j][1] * alpha);
            float2 r1 = make_float2(acc[i][j][2] * alpha, acc[i][j][3] * alpha);
            if (Msk) {
                r0.x += Msk[(long long)m * ldm + n];
                r0.y += Msk[(long long)m * ldm + n + 1];
                r1.x += Msk[(long long)(m + 8) * ldm + n];
                r1.y += Msk[(long long)(m + 8) * ldm + n + 1];
            }
            if (D) {
                r0.x += D[(long long)m * ldd + n];
                r0.y += D[(long long)m * ldd + n + 1];
                r1.x += D[(long long)(m + 8) * ldd + n];
                r1.y += D[(long long)(m + 8) * ldd + n + 1];
            }
            *reinterpret_cast<float2*>(&C[(long long)m * ldc + n]) = r0;
            *reinterpret_cast<float2*>(&C[(long long)(m + 8) * ldc + n]) = r1;
        }
    }
}

// --------------------------- elementwise kernels ---------------------------
__global__ void rmsnorm_kernel(const float* __restrict__ x,
                               const float* __restrict__ w,
                               float* __restrict__ out, int ncols)
{
    int row = blockIdx.x;
    const float* xr = x + (long long)row * ncols;
    float* orow = out + (long long)row * ncols;
    __shared__ float red[256];
    int tid = threadIdx.x;
    float s = 0.f;
    for (int i = tid; i < ncols; i += 256) { float v = xr[i]; s += v * v; }
    red[tid] = s; __syncthreads();
    for (int k = 128; k > 0; k >>= 1) {
        if (tid < k) red[tid] += red[tid + k];
        __syncthreads();
    }
    float scale = rsqrtf(red[0] / (float)ncols + 1e-6f);
    for (int i = tid; i < ncols; i += 256)
        orow[i] = xr[i] * scale * (1.0f + w[i]);
}

__global__ void rope_kernel(const float* __restrict__ q, const float* __restrict__ k,
                            float* __restrict__ qr, float* __restrict__ kr)
{
    int s = blockIdx.x;                              // 0..S-1
    int idx = blockIdx.y * 256 + threadIdx.x;        // 0..1023 (NH*HD)
    int d = idx & (HD - 1);
    long long base = (long long)s * HID + idx;
    int i = d & 63;
    float freq = powf(10000.0f, -(float)i / 64.0f);
    float ang = (float)s * freq;
    float c = cosf(ang), sn = sinf(ang);
    float qv = q[base], kv = k[base];
    float qo, ko;
    if (d < 64) {
        qo = qv * c - q[base + 64] * sn;
        ko = kv * c - k[base + 64] * sn;
    } else {
        qo = qv * c + q[base - 64] * sn;
        ko = kv * c + k[base - 64] * sn;
    }
    qr[base] = qo;
    kr[base] = ko;
}

__global__ void softmax_rows(float* __restrict__ S, int len)
{
    long long row = blockIdx.x;
    float4* p = reinterpret_cast<float4*>(S + row * (long long)len);
    int n4 = len >> 2;
    __shared__ float red[256];
    int tid = threadIdx.x;

    float mx = -1e30f;
    for (int i = tid; i < n4; i += 256) {
        float4 v = p[i];
        mx = fmaxf(mx, fmaxf(fmaxf(v.x, v.y), fmaxf(v.z, v.w)));
    }
    red[tid] = mx; __syncthreads();
    for (int k = 128; k > 0; k >>= 1) {
        if (tid < k) red[tid] = fmaxf(red[tid], red[tid + k]);
        __syncthreads();
    }
    mx = red[0];
    __syncthreads();

    float sum = 0.f;
    for (int i = tid; i < n4; i += 256) {
        float4 v = p[i];
        v.x = __expf(v.x - mx); v.y = __expf(v.y - mx);
        v.z = __expf(v.z - mx); v.w = __expf(v.w - mx);
        p[i] = v;
        sum += v.x + v.y + v.z + v.w;
    }
    red[tid] = sum; __syncthreads();
    for (int k = 128; k > 0; k >>= 1) {
        if (tid < k) red[tid] += red[tid + k];
        __syncthreads();
    }
    float inv = 1.0f / red[0];
    for (int i = tid; i < n4; i += 256) {
        float4 v = p[i];
        v.x *= inv; v.y *= inv; v.z *= inv; v.w *= inv;
        p[i] = v;
    }
}

__global__ void gelumul_kernel(float* __restrict__ g, const float* __restrict__ u,
                               long long n)
{
    long long i = (long long)blockIdx.x * 256 + threadIdx.x;
    if (i < n) {
        float x = g[i];
        float t = tanhf(0.7978845608028654f * (x + 0.044715f * x * x * x));
        g[i] = 0.5f * x * (1.0f + t) * u[i];
    }
}

// ------------------------------- host side ---------------------------------
static inline void gemm_nn(const float* A, int lda, long long sA,
                           const float* B, int ldb, long long sB,
                           float* C, int ldc, long long sC,
                           const float* D, int ldd, long long sD,
                           const float* Msk, int ldm,
                           float alpha, int M, int N, int K, int batch)
{
    dim3 grid(N / 128, M / 128, batch);
    tf32_gemm<false><<<grid, 256>>>(A, lda, sA, B, ldb, sB, C, ldc, sC,
                                    D, ldd, sD, Msk, ldm, alpha, M, N, K);
}

static inline void gemm_nt(const float* A, int lda, long long sA,
                           const float* B, int ldb, long long sB,
                           float* C, int ldc, long long sC,
                           const float* Msk, int ldm,
                           float alpha, int M, int N, int K, int batch)
{
    dim3 grid(N / 128, M / 128, batch);
    tf32_gemm<true><<<grid, 256>>>(A, lda, sA, B, ldb, sB, C, ldc, sC,
                                   (const float*)nullptr, 0, 0, Msk, ldm,
                                   alpha, M, N, K);
}

extern "C" void kernel_launch(void* const* d_in, const int* in_sizes, int n_in,
                              void* d_out, int out_size)
{
    (void)in_sizes; (void)n_in; (void)out_size;

    const float* x[2]    = { (const float*)d_in[0], (const float*)d_in[1] };
    const float* mask[2] = { (const float*)d_in[2], (const float*)d_in[3] };
    const float* mixmask = (const float*)d_in[4];
    float* out = (float*)d_out;

    float *p_h, *p_q, *p_k, *p_v, *p_qr, *p_kr, *p_sc, *p_at, *p_h1, *p_m, *p_g, *p_u;
    cudaGetSymbolAddress((void**)&p_h,  g_h);
    cudaGetSymbolAddress((void**)&p_q,  g_q);
    cudaGetSymbolAddress((void**)&p_k,  g_k);
    cudaGetSymbolAddress((void**)&p_v,  g_v);
    cudaGetSymbolAddress((void**)&p_qr, g_qr);
    cudaGetSymbolAddress((void**)&p_kr, g_kr);
    cudaGetSymbolAddress((void**)&p_sc, g_scores);
    cudaGetSymbolAddress((void**)&p_at, g_attn);
    cudaGetSymbolAddress((void**)&p_h1, g_h1);
    cudaGetSymbolAddress((void**)&p_m,  g_m);
    cudaGetSymbolAddress((void**)&p_g,  g_gate);
    cudaGetSymbolAddress((void**)&p_u,  g_up);

    const float att_scale = 0.08838834764831845f;   // 1/sqrt(128)
    const long long EOFF = (long long)S_LEN * HID;

    for (int e = 0; e < 2; e++) {
        const float* w_ln  = (const float*)d_in[5 + 9 * e + 0];
        const float* w_q   = (const float*)d_in[5 + 9 * e + 1];
        const float* w_k   = (const float*)d_in[5 + 9 * e + 2];
        const float* w_v   = (const float*)d_in[5 + 9 * e + 3];
        const float* w_o   = (const float*)d_in[5 + 9 * e + 4];
        const float* w_pln = (const float*)d_in[5 + 9 * e + 5];
        const float* w_g   = (const float*)d_in[5 + 9 * e + 6];
        const float* w_u   = (const float*)d_in[5 + 9 * e + 7];
        const float* w_d   = (const float*)d_in[5 + 9 * e + 8];

        float* q_e = p_q + e * EOFF;
        float* k_e = p_k + e * EOFF;
        float* v_e = p_v + e * EOFF;
        float* h1_e = p_h1 + e * EOFF;
        float* out_e = out + e * EOFF;

        // 1. pre-attention RMSNorm
        rmsnorm_kernel<<<S_LEN, 256>>>(x[e], w_ln, p_h, HID);

        // 2. q/k/v projections (pre-RoPE, kept for mix attention)
        gemm_nn(p_h, HID, 0, w_q, HID, 0, q_e, HID, 0,
                nullptr, 0, 0, nullptr, 0, 1.0f, S_LEN, HID, HID, 1);
        gemm_nn(p_h, HID, 0, w_k, HID, 0, k_e, HID, 0,
                nullptr, 0, 0, nullptr, 0, 1.0f, S_LEN, HID, HID, 1);
        gemm_nn(p_h, HID, 0, w_v, HID, 0, v_e, HID, 0,
                nullptr, 0, 0, nullptr, 0, 1.0f, S_LEN, HID, HID, 1);

        // 3. RoPE
        rope_kernel<<<dim3(S_LEN, 4), 256>>>(q_e, k_e, p_qr, p_kr);

        // 4. scores = qr @ kr^T * scale + mask   (batched over heads)
        gemm_nt(p_qr, HID, HD, p_kr, HID, HD,
                p_sc, S_LEN, (long long)S_LEN * S_LEN,
                mask[e], S_LEN, att_scale, S_LEN, S_LEN, HD, NH);

        // 5. softmax
        softmax_rows<<<NH * S_LEN, 256>>>(p_sc, S_LEN);

        // 6. attn = probs @ v    (batched over heads)
        gemm_nn(p_sc, S_LEN, (long long)S_LEN * S_LEN,
                v_e, HID, HD,
                p_at, HID, HD,
                nullptr, 0, 0, nullptr, 0, 1.0f, S_LEN, HD, S_LEN, NH);

        // 7. h1 = attn @ w_o + x
        gemm_nn(p_at, HID, 0, w_o, HID, 0, h1_e, HID, 0,
                x[e], HID, 0, nullptr, 0, 1.0f, S_LEN, HID, HID, 1);

        // 8. post-attention RMSNorm
        rmsnorm_kernel<<<S_LEN, 256>>>(h1_e, w_pln, p_m, HID);

        // 9. MLP
        gemm_nn(p_m, HID, 0, w_g, INTER, 0, p_g, INTER, 0,
                nullptr, 0, 0, nullptr, 0, 1.0f, S_LEN, INTER, HID, 1);
        gemm_nn(p_m, HID, 0, w_u, INTER, 0, p_u, INTER, 0,
                nullptr, 0, 0, nullptr, 0, 1.0f, S_LEN, INTER, HID, 1);
        gelumul_kernel<<<(S_LEN * INTER) / 256, 256>>>(p_g, p_u,
                                                       (long long)S_LEN * INTER);
        gemm_nn(p_g, INTER, 0, w_d, HID, 0, out_e, HID, 0,
                h1_e, HID, 0, nullptr, 0, 1.0f, S_LEN, HID, INTER, 1);
    }

    // ----- mix attention over concatenated PRE-RoPE q/k/v -----
    gemm_nt(p_q, HID, HD, p_k, HID, HD,
            p_sc, S2, (long long)S2 * S2,
            mixmask, S2, att_scale, S2, S2, HD, NH);
    softmax_rows<<<NH * S2, 256>>>(p_sc, S2);
    gemm_nn(p_sc, S2, (long long)S2 * S2,
            p_v, HID, HD,
            p_at, HID, HD,
            nullptr, 0, 0, nullptr, 0, 1.0f, S2, HD, S2, NH);

    // final: out_e += mixed_e @ w_o_e
    for (int e = 0; e < 2; e++) {
        const float* w_o = (const float*)d_in[5 + 9 * e + 4];
        float* out_e = out + e * EOFF;
        gemm_nn(p_at + e * EOFF, HID, 0, w_o, HID, 0, out_e, HID, 0,
                out_e, HID, 0, nullptr, 0, 1.0f, S_LEN, HID, HID, 1);
    }
}

// round 17
// speedup vs baseline: 1.0037x; 1.0036x over previous
#include <cuda_runtime.h>
#include <cuda_bf16.h>
#include <math.h>
#include <stdint.h>

// ---------------------------------------------------------------------------
// GemmaMoELayer: two Gemma decoder layers (a/b) + mix attention over
// concatenated pre-RoPE q/k/v, outputs stacked [2, S, HID] fp32.
// All GEMMs on tensor cores via mma.sync tf32 (fp32 accumulate).
// B=1, S=2048, HID=1024, NH=8, HD=128, INTER=4096
// ---------------------------------------------------------------------------

#define S_LEN 2048
#define HID 1024
#define NH 8
#define HD 128
#define INTER 4096
#define S2 (2 * S_LEN)   // 4096

// ------------------------- scratch (device globals) ------------------------
__device__ float g_h[S_LEN * HID];                 // rmsnorm output
__device__ float g_q[S2 * HID];                    // pre-RoPE q, both experts
__device__ float g_k[S2 * HID];
__device__ float g_v[S2 * HID];
__device__ float g_qr[S_LEN * HID];                // post-RoPE (per expert)
__device__ float g_kr[S_LEN * HID];
__device__ float g_scores[(long long)NH * S2 * S2];  // 536 MB, reused
__device__ float g_attn[S2 * HID];
__device__ float g_h1[2 * S_LEN * HID];
__device__ float g_m[S_LEN * HID];
__device__ float g_gate[S_LEN * INTER];
__device__ float g_up[S_LEN * INTER];

// ----------------------------- tf32 helpers --------------------------------
__device__ __forceinline__ uint32_t f2tf(float f) {
    uint32_t u;
    asm("cvt.rna.tf32.f32 %0, %1;" : "=r"(u) : "f"(f));
    return u;
}

__device__ __forceinline__ void mma_tf32(float* c, const uint32_t* a,
                                         const uint32_t* b) {
    asm volatile(
        "mma.sync.aligned.m16n8k8.row.col.f32.tf32.tf32.f32 "
        "{%0,%1,%2,%3}, {%4,%5,%6,%7}, {%8,%9}, {%0,%1,%2,%3};\n"
        : "+f"(c[0]), "+f"(c[1]), "+f"(c[2]), "+f"(c[3])
        : "r"(a[0]), "r"(a[1]), "r"(a[2]), "r"(a[3]),
          "r"(b[0]), "r"(b[1]));
}

// --------------------------- TF32 GEMM kernel ------------------------------
// C[m,n] = alpha * sum_k A[m,k] * (TB ? B[n,k] : B[k,n]) (+Msk) (+D)
// Block tile 128x128, K-tile 16, 256 threads (8 warps: 2 m-rows x 4 n-cols,
// warp tile 64x32). M,N % 128 == 0, K % 16 == 0. Batched via blockIdx.z.
template <bool TB>
__global__ __launch_bounds__(256, 1)
void tf32_gemm(const float* __restrict__ A, int lda, long long sA,
               const float* __restrict__ B, int ldb, long long sB,
               float* __restrict__ C, int ldc, long long sC,
               const float* __restrict__ D, int ldd, long long sD,
               const float* __restrict__ Msk, int ldm,
               float alpha, int M, int N, int K)
{
    __shared__ uint32_t As[2][16][136];   // [k][m], pad 8 -> conflict-free frags
    __shared__ uint32_t Bs[2][16][136];   // [k][n]

    const int bz = blockIdx.z;
    A += bz * sA;
    B += bz * sB;
    C += bz * sC;
    if (D) D += bz * sD;

    const int tid  = threadIdx.x;
    const int warp = tid >> 5, lane = tid & 31;
    const int gid  = lane >> 2, tig = lane & 3;
    const int wm   = (warp >> 2) * 64;    // 0 / 64
    const int wn   = (warp & 3) * 32;     // 0 / 32 / 64 / 96
    const int m0   = blockIdx.y * 128;
    const int n0   = blockIdx.x * 128;

    // staging thread mapping
    const int ar = tid >> 2;             // 0..63 (A rows; + second pass +64)
    const int ac = (tid & 3) * 4;        // k offset within tile
    int br, bc;
    if (TB) { br = tid >> 2;  bc = (tid & 3) * 4;  }  // br = n idx, bc = k
    else    { br = tid >> 4;  bc = (tid & 15) * 4; }  // br = k idx, bc = n

    float acc[4][4][4] = {};

    float4 ga[2], gb[2];

    // ---- prologue: load k-tile 0 ----
    ga[0] = *reinterpret_cast<const float4*>(&A[(long long)(m0 + ar) * lda + ac]);
    ga[1] = *reinterpret_cast<const float4*>(&A[(long long)(m0 + ar + 64) * lda + ac]);
    if (TB) {
        gb[0] = *reinterpret_cast<const float4*>(&B[(long long)(n0 + br) * ldb + bc]);
        gb[1] = *reinterpret_cast<const float4*>(&B[(long long)(n0 + br + 64) * ldb + bc]);
    } else {
        gb[0] = *reinterpret_cast<const float4*>(&B[(long long)br * ldb + n0 + bc]);
        gb[1] = *reinterpret_cast<const float4*>(&B[(long long)br * ldb + n0 + bc + 64]);
    }

    {
        float a0[4] = {ga[0].x, ga[0].y, ga[0].z, ga[0].w};
        float a1[4] = {ga[1].x, ga[1].y, ga[1].z, ga[1].w};
        float b0[4] = {gb[0].x, gb[0].y, gb[0].z, gb[0].w};
        float b1[4] = {gb[1].x, gb[1].y, gb[1].z, gb[1].w};
#pragma unroll
        for (int u = 0; u < 4; u++) {
            As[0][ac + u][ar]      = f2tf(a0[u]);
            As[0][ac + u][ar + 64] = f2tf(a1[u]);
            if (TB) {
                Bs[0][bc + u][br]      = f2tf(b0[u]);
                Bs[0][bc + u][br + 64] = f2tf(b1[u]);
            } else {
                Bs[0][br][bc + u]      = f2tf(b0[u]);
                Bs[0][br][bc + 64 + u] = f2tf(b1[u]);
            }
        }
    }
    __syncthreads();

    const int nk = K >> 4;
    for (int kt = 0; kt < nk; kt++) {
        const int buf = kt & 1;
        const bool more = (kt + 1 < nk);

        // issue next tile's global loads (latency hidden by compute below)
        if (more) {
            const int kn = (kt + 1) << 4;
            ga[0] = *reinterpret_cast<const float4*>(&A[(long long)(m0 + ar) * lda + kn + ac]);
            ga[1] = *reinterpret_cast<const float4*>(&A[(long long)(m0 + ar + 64) * lda + kn + ac]);
            if (TB) {
                gb[0] = *reinterpret_cast<const float4*>(&B[(long long)(n0 + br) * ldb + kn + bc]);
                gb[1] = *reinterpret_cast<const float4*>(&B[(long long)(n0 + br + 64) * ldb + kn + bc]);
            } else {
                gb[0] = *reinterpret_cast<const float4*>(&B[(long long)(kn + br) * ldb + n0 + bc]);
                gb[1] = *reinterpret_cast<const float4*>(&B[(long long)(kn + br) * ldb + n0 + bc + 64]);
            }
        }

        // ---- compute on current buffer: 2 k-steps of 8 ----
#pragma unroll
        for (int ks = 0; ks < 2; ks++) {
            const int kk = ks * 8;
            uint32_t af[4][4], bf[4][2];
#pragma unroll
            for (int i = 0; i < 4; i++) {
                const int m = wm + i * 16 + gid;
                af[i][0] = As[buf][kk + tig][m];
                af[i][1] = As[buf][kk + tig][m + 8];
                af[i][2] = As[buf][kk + tig + 4][m];
                af[i][3] = As[buf][kk + tig + 4][m + 8];
            }
#pragma unroll
            for (int j = 0; j < 4; j++) {
                const int n = wn + j * 8 + gid;
                bf[j][0] = Bs[buf][kk + tig][n];
                bf[j][1] = Bs[buf][kk + tig + 4][n];
            }
#pragma unroll
            for (int i = 0; i < 4; i++)
#pragma unroll
                for (int j = 0; j < 4; j++)
                    mma_tf32(acc[i][j], af[i], bf[j]);
        }

        // ---- stage next tile ----
        if (more) {
            const int nb = buf ^ 1;
            float a0[4] = {ga[0].x, ga[0].y, ga[0].z, ga[0].w};
            float a1[4] = {ga[1].x, ga[1].y, ga[1].z, ga[1].w};
            float b0[4] = {gb[0].x, gb[0].y, gb[0].z, gb[0].w};
            float b1[4] = {gb[1].x, gb[1].y, gb[1].z, gb[1].w};
#pragma unroll
            for (int u = 0; u < 4; u++) {
                As[nb][ac + u][ar]      = f2tf(a0[u]);
                As[nb][ac + u][ar + 64] = f2tf(a1[u]);
                if (TB) {
                    Bs[nb][bc + u][br]      = f2tf(b0[u]);
                    Bs[nb][bc + u][br + 64] = f2tf(b1[u]);
                } else {
                    Bs[nb][br][bc + u]      = f2tf(b0[u]);
                    Bs[nb][br][bc + 64 + u] = f2tf(b1[u]);
                }
            }
        }
        __syncthreads();
    }

    // -------- epilogue --------
#pragma unroll
    for (int i = 0; i < 4; i++) {
#pragma unroll
        for (int j = 0; j < 4; j++) {
            const int m = m0 + wm + i * 16 + gid;
            const int n = n0 + wn + j * 8 + tig * 2;
            float2 r0 = make_float2(acc[i][j][0] * alpha, acc[i][j][1] * alpha);
            float2 r1 = make_float2(acc[i][j][2] * alpha, acc[i][j][3] * alpha);
            if (Msk) {
                r0.x += Msk[(long long)m * ldm + n];
                r0.y += Msk[(long long)m * ldm + n + 1];
                r1.x += Msk[(long long)(m + 8) * ldm + n];
                r1.y += Msk[(long long)(m + 8) * ldm + n + 1];
            }
            if (D) {
                r0.x += D[(long long)m * ldd + n];
                r0.y += D[(long long)m * ldd + n + 1];
                r1.x += D[(long long)(m + 8) * ldd + n];
                r1.y += D[(long long)(m + 8) * ldd + n + 1];
            }
            *reinterpret_cast<float2*>(&C[(long long)m * ldc + n]) = r0;
            *reinterpret_cast<float2*>(&C[(long long)(m + 8) * ldc + n]) = r1;
        }
    }
}

// --------------------------- elementwise kernels ---------------------------
__global__ void rmsnorm_kernel(const float* __restrict__ x,
                               const float* __restrict__ w,
                               float* __restrict__ out, int ncols)
{
    int row = blockIdx.x;
    const float* xr = x + (long long)row * ncols;
    float* orow = out + (long long)row * ncols;
    __shared__ float red[256];
    int tid = threadIdx.x;
    float s = 0.f;
    for (int i = tid; i < ncols; i += 256) { float v = xr[i]; s += v * v; }
    red[tid] = s; __syncthreads();
    for (int k = 128; k > 0; k >>= 1) {
        if (tid < k) red[tid] += red[tid + k];
        __syncthreads();
    }
    float scale = rsqrtf(red[0] / (float)ncols + 1e-6f);
    for (int i = tid; i < ncols; i += 256)
        orow[i] = xr[i] * scale * (1.0f + w[i]);
}

__global__ void rope_kernel(const float* __restrict__ q, const float* __restrict__ k,
                            float* __restrict__ qr, float* __restrict__ kr)
{
    int s = blockIdx.x;                              // 0..S-1
    int idx = blockIdx.y * 256 + threadIdx.x;        // 0..1023 (NH*HD)
    int d = idx & (HD - 1);
    long long base = (long long)s * HID + idx;
    int i = d & 63;
    float freq = powf(10000.0f, -(float)i / 64.0f);
    float ang = (float)s * freq;
    float c = cosf(ang), sn = sinf(ang);
    float qv = q[base], kv = k[base];
    float qo, ko;
    if (d < 64) {
        qo = qv * c - q[base + 64] * sn;
        ko = kv * c - k[base + 64] * sn;
    } else {
        qo = qv * c + q[base - 64] * sn;
        ko = kv * c + k[base - 64] * sn;
    }
    qr[base] = qo;
    kr[base] = ko;
}

__global__ void softmax_rows(float* __restrict__ S, int len)
{
    long long row = blockIdx.x;
    float4* p = reinterpret_cast<float4*>(S + row * (long long)len);
    int n4 = len >> 2;
    __shared__ float red[256];
    int tid = threadIdx.x;

    float mx = -1e30f;
    for (int i = tid; i < n4; i += 256) {
        float4 v = p[i];
        mx = fmaxf(mx, fmaxf(fmaxf(v.x, v.y), fmaxf(v.z, v.w)));
    }
    red[tid] = mx; __syncthreads();
    for (int k = 128; k > 0; k >>= 1) {
        if (tid < k) red[tid] = fmaxf(red[tid], red[tid + k]);
        __syncthreads();
    }
    mx = red[0];
    __syncthreads();

    float sum = 0.f;
    for (int i = tid; i < n4; i += 256) {
        float4 v = p[i];
        v.x = __expf(v.x - mx); v.y = __expf(v.y - mx);
        v.z = __expf(v.z - mx); v.w = __expf(v.w - mx);
        p[i] = v;
        sum += v.x + v.y + v.z + v.w;
    }
    red[tid] = sum; __syncthreads();
    for (int k = 128; k > 0; k >>= 1) {
        if (tid < k) red[tid] += red[tid + k];
        __syncthreads();
    }
    float inv = 1.0f / red[0];
    for (int i = tid; i < n4; i += 256) {
        float4 v = p[i];
        v.x *= inv; v.y *= inv; v.z *= inv; v.w *= inv;
        p[i] = v;
    }
}

__global__ void gelumul_kernel(float* __restrict__ g, const float* __restrict__ u,
                               long long n)
{
    long long i = (long long)blockIdx.x * 256 + threadIdx.x;
    if (i < n) {
        float x = g[i];
        float t = tanhf(0.7978845608028654f * (x + 0.044715f * x * x * x));
        g[i] = 0.5f * x * (1.0f + t) * u[i];
    }
}

// ------------------------------- host side ---------------------------------
static inline void gemm_nn(const float* A, int lda, long long sA,
                           const float* B, int ldb, long long sB,
                           float* C, int ldc, long long sC,
                           const float* D, int ldd, long long sD,
                           const float* Msk, int ldm,
                           float alpha, int M, int N, int K, int batch)
{
    dim3 grid(N / 128, M / 128, batch);
    tf32_gemm<false><<<grid, 256>>>(A, lda, sA, B, ldb, sB, C, ldc, sC,
                                    D, ldd, sD, Msk, ldm, alpha, M, N, K);
}

static inline void gemm_nt(const float* A, int lda, long long sA,
                           const float* B, int ldb, long long sB,
                           float* C, int ldc, long long sC,
                           const float* Msk, int ldm,
                           float alpha, int M, int N, int K, int batch)
{
    dim3 grid(N / 128, M / 128, batch);
    tf32_gemm<true><<<grid, 256>>>(A, lda, sA, B, ldb, sB, C, ldc, sC,
                                   (const float*)nullptr, 0, 0, Msk, ldm,
                                   alpha, M, N, K);
}

extern "C" void kernel_launch(void* const* d_in, const int* in_sizes, int n_in,
                              void* d_out, int out_size)
{
    (void)in_sizes; (void)n_in; (void)out_size;

    const float* x[2]    = { (const float*)d_in[0], (const float*)d_in[1] };
    const float* mask[2] = { (const float*)d_in[2], (const float*)d_in[3] };
    const float* mixmask = (const float*)d_in[4];
    float* out = (float*)d_out;

    float *p_h, *p_q, *p_k, *p_v, *p_qr, *p_kr, *p_sc, *p_at, *p_h1, *p_m, *p_g, *p_u;
    cudaGetSymbolAddress((void**)&p_h,  g_h);
    cudaGetSymbolAddress((void**)&p_q,  g_q);
    cudaGetSymbolAddress((void**)&p_k,  g_k);
    cudaGetSymbolAddress((void**)&p_v,  g_v);
    cudaGetSymbolAddress((void**)&p_qr, g_qr);
    cudaGetSymbolAddress((void**)&p_kr, g_kr);
    cudaGetSymbolAddress((void**)&p_sc, g_scores);
    cudaGetSymbolAddress((void**)&p_at, g_attn);
    cudaGetSymbolAddress((void**)&p_h1, g_h1);
    cudaGetSymbolAddress((void**)&p_m,  g_m);
    cudaGetSymbolAddress((void**)&p_g,  g_gate);
    cudaGetSymbolAddress((void**)&p_u,  g_up);

    const float att_scale = 0.08838834764831845f;   // 1/sqrt(128)
    const long long EOFF = (long long)S_LEN * HID;

    for (int e = 0; e < 2; e++) {
        const float* w_ln  = (const float*)d_in[5 + 9 * e + 0];
        const float* w_q   = (const float*)d_in[5 + 9 * e + 1];
        const float* w_k   = (const float*)d_in[5 + 9 * e + 2];
        const float* w_v   = (const float*)d_in[5 + 9 * e + 3];
        const float* w_o   = (const float*)d_in[5 + 9 * e + 4];
        const float* w_pln = (const float*)d_in[5 + 9 * e + 5];
        const float* w_g   = (const float*)d_in[5 + 9 * e + 6];
        const float* w_u   = (const float*)d_in[5 + 9 * e + 7];
        const float* w_d   = (const float*)d_in[5 + 9 * e + 8];

        float* q_e = p_q + e * EOFF;
        float* k_e = p_k + e * EOFF;
        float* v_e = p_v + e * EOFF;
        float* h1_e = p_h1 + e * EOFF;
        float* out_e = out + e * EOFF;

        // 1. pre-attention RMSNorm
        rmsnorm_kernel<<<S_LEN, 256>>>(x[e], w_ln, p_h, HID);

        // 2. q/k/v projections (pre-RoPE, kept for mix attention)
        gemm_nn(p_h, HID, 0, w_q, HID, 0, q_e, HID, 0,
                nullptr, 0, 0, nullptr, 0, 1.0f, S_LEN, HID, HID, 1);
        gemm_nn(p_h, HID, 0, w_k, HID, 0, k_e, HID, 0,
                nullptr, 0, 0, nullptr, 0, 1.0f, S_LEN, HID, HID, 1);
        gemm_nn(p_h, HID, 0, w_v, HID, 0, v_e, HID, 0,
                nullptr, 0, 0, nullptr, 0, 1.0f, S_LEN, HID, HID, 1);

        // 3. RoPE
        rope_kernel<<<dim3(S_LEN, 4), 256>>>(q_e, k_e, p_qr, p_kr);

        // 4. scores = qr @ kr^T * scale + mask   (batched over heads)
        gemm_nt(p_qr, HID, HD, p_kr, HID, HD,
                p_sc, S_LEN, (long long)S_LEN * S_LEN,
                mask[e], S_LEN, att_scale, S_LEN, S_LEN, HD, NH);

        // 5. softmax
        softmax_rows<<<NH * S_LEN, 256>>>(p_sc, S_LEN);

        // 6. attn = probs @ v    (batched over heads)
        gemm_nn(p_sc, S_LEN, (long long)S_LEN * S_LEN,
                v_e, HID, HD,
                p_at, HID, HD,
                nullptr, 0, 0, nullptr, 0, 1.0f, S_LEN, HD, S_LEN, NH);

        // 7. h1 = attn @ w_o + x
        gemm_nn(p_at, HID, 0, w_o, HID, 0, h1_e, HID, 0,
                x[e], HID, 0, nullptr, 0, 1.0f, S_LEN, HID, HID, 1);

        // 8. post-attention RMSNorm
        rmsnorm_kernel<<<S_LEN, 256>>>(h1_e, w_pln, p_m, HID);

        // 9. MLP
        gemm_nn(p_m, HID, 0, w_g, INTER, 0, p_g, INTER, 0,
                nullptr, 0, 0, nullptr, 0, 1.0f, S_LEN, INTER, HID, 1);
        gemm_nn(p_m, HID, 0, w_u, INTER, 0, p_u, INTER, 0,
                nullptr, 0, 0, nullptr, 0, 1.0f, S_LEN, INTER, HID, 1);
        gelumul_kernel<<<(S_LEN * INTER) / 256, 256>>>(p_g, p_u,
                                                       (long long)S_LEN * INTER);
        gemm_nn(p_g, INTER, 0, w_d, HID, 0, out_e, HID, 0,
                h1_e, HID, 0, nullptr, 0, 1.0f, S_LEN, HID, INTER, 1);
    }

    // ----- mix attention over concatenated PRE-RoPE q/k/v -----
    gemm_nt(p_q, HID, HD, p_k, HID, HD,
            p_sc, S2, (long long)S2 * S2,
            mixmask, S2, att_scale, S2, S2, HD, NH);
    softmax_rows<<<NH * S2, 256>>>(p_sc, S2);
    gemm_nn(p_sc, S2, (long long)S2 * S2,
            p_v, HID, HD,
            p_at, HID, HD,
            nullptr, 0, 0, nullptr, 0, 1.0f, S2, HD, S2, NH);

    // final: out_e += mixed_e @ w_o_e
    for (int e = 0; e < 2; e++) {
        const float* w_o = (const float*)d_in[5 + 9 * e + 4];
        float* out_e = out + e * EOFF;
        gemm_nn(p_at + e * EOFF, HID, 0, w_o, HID, 0, out_e, HID, 0,
                out_e, HID, 0, nullptr, 0, 1.0f, S_LEN, HID, HID, 1);
    }
}